// round 1
// baseline (speedup 1.0000x reference)
#include <cuda_runtime.h>
#include <math.h>

// Problem constants
#define S_STEPS 24     // number of prefix steps == T
#define BATCH   128
#define SEQT    24
#define DIN     512
#define D       128
#define DFF     2048
#define NH      4
#define DH      32
#define NC      64
#define NT      38400  // BATCH * S*(S+1)/2 = 128*300
#define NBT     3072   // BATCH*SEQT

// Scratch (device globals; allocation-free per harness rules)
__device__ float g_h0[NBT * D];
__device__ float g_Y[NT * D];
__device__ float g_qkv[NT * 3 * D];
__device__ float g_ctx[NT * D];
__device__ float g_proj[NT * D];
__device__ float g_H[(size_t)NT * DFF];
__device__ float g_last[NBT * D];

// ---------------------------------------------------------------------------
// SGEMM: C[M,N] = A[M,K] @ W[N,K]^T + bias[N], optional ReLU.
// BM=BN=128, BK=16, 256 threads, 8x8 microtile. All dims divide evenly here.
// ---------------------------------------------------------------------------
#define BM 128
#define BN 128
#define BK 16

__global__ __launch_bounds__(256) void sgemm_bias(
    const float* __restrict__ A, const float* __restrict__ W,
    const float* __restrict__ bias, float* __restrict__ C,
    int M, int N, int K, int relu)
{
    __shared__ float As[BK][BM];
    __shared__ float Ws[BK][BN];

    const int m0 = blockIdx.y * BM;
    const int n0 = blockIdx.x * BN;
    const int t  = threadIdx.x;
    const int tx = t & 15;
    const int ty = t >> 4;

    float acc[8][8];
#pragma unroll
    for (int i = 0; i < 8; ++i)
#pragma unroll
        for (int j = 0; j < 8; ++j) acc[i][j] = 0.f;

    const float* Ap = A + (size_t)m0 * K;
    const float* Wp = W + (size_t)n0 * K;

    for (int k0 = 0; k0 < K; k0 += BK) {
#pragma unroll
        for (int r = 0; r < 2; ++r) {
            int idx = t + r * 256;          // 512 float4 loads per operand tile
            int row = idx >> 2;
            int c4  = (idx & 3) * 4;
            float4 av = *(const float4*)(Ap + (size_t)row * K + k0 + c4);
            As[c4 + 0][row] = av.x; As[c4 + 1][row] = av.y;
            As[c4 + 2][row] = av.z; As[c4 + 3][row] = av.w;
            float4 wv = *(const float4*)(Wp + (size_t)row * K + k0 + c4);
            Ws[c4 + 0][row] = wv.x; Ws[c4 + 1][row] = wv.y;
            Ws[c4 + 2][row] = wv.z; Ws[c4 + 3][row] = wv.w;
        }
        __syncthreads();

#pragma unroll
        for (int kk = 0; kk < BK; ++kk) {
            float a[8], w[8];
            *(float4*)(a + 0) = *(const float4*)&As[kk][ty * 4];
            *(float4*)(a + 4) = *(const float4*)&As[kk][64 + ty * 4];
            *(float4*)(w + 0) = *(const float4*)&Ws[kk][tx * 4];
            *(float4*)(w + 4) = *(const float4*)&Ws[kk][64 + tx * 4];
#pragma unroll
            for (int i = 0; i < 8; ++i)
#pragma unroll
                for (int j = 0; j < 8; ++j) acc[i][j] += a[i] * w[j];
        }
        __syncthreads();
    }

    float b0[4], b1[4];
    *(float4*)b0 = *(const float4*)(bias + n0 + tx * 4);
    *(float4*)b1 = *(const float4*)(bias + n0 + 64 + tx * 4);

#pragma unroll
    for (int i = 0; i < 8; ++i) {
        int m = m0 + ((i < 4) ? 0 : 64) + ty * 4 + (i & 3);
        float4 v0, v1;
        v0.x = acc[i][0] + b0[0]; v0.y = acc[i][1] + b0[1];
        v0.z = acc[i][2] + b0[2]; v0.w = acc[i][3] + b0[3];
        v1.x = acc[i][4] + b1[0]; v1.y = acc[i][5] + b1[1];
        v1.z = acc[i][6] + b1[2]; v1.w = acc[i][7] + b1[3];
        if (relu) {
            v0.x = fmaxf(v0.x, 0.f); v0.y = fmaxf(v0.y, 0.f);
            v0.z = fmaxf(v0.z, 0.f); v0.w = fmaxf(v0.w, 0.f);
            v1.x = fmaxf(v1.x, 0.f); v1.y = fmaxf(v1.y, 0.f);
            v1.z = fmaxf(v1.z, 0.f); v1.w = fmaxf(v1.w, 0.f);
        }
        *(float4*)(C + (size_t)m * N + n0 + tx * 4)      = v0;
        *(float4*)(C + (size_t)m * N + n0 + 64 + tx * 4) = v1;
    }
}

// ---------------------------------------------------------------------------
// Positional encoding add: g_h0[b*T+t][d] += pe(t,d)
// ---------------------------------------------------------------------------
__global__ void add_pe_kernel()
{
    int n = blockIdx.x;           // b*SEQT + t
    int t = n % SEQT;
    int d = threadIdx.x;          // 0..127
    float freq = expf((float)(d & ~1) * (-9.210340371976184f / 128.f));
    float arg  = (float)t * freq;
    float pe   = (d & 1) ? cosf(arg) : sinf(arg);
    g_h0[n * D + d] += pe;
}

// ---------------------------------------------------------------------------
// Scatter h0 to packed token layout: token n -> (s, b, t)
// off(s) = 64*s*(s+1); within step: b*(s+1)+t
// ---------------------------------------------------------------------------
__global__ void scatter_kernel()
{
    int n = blockIdx.x;
    int s = 0;
    while (n >= 64 * (s + 1) * (s + 2)) s++;
    int r = n - 64 * s * (s + 1);
    int P = s + 1;
    int b = r / P;
    int t = r - b * P;
    g_Y[n * D + threadIdx.x] = g_h0[(b * SEQT + t) * D + threadIdx.x];
}

// ---------------------------------------------------------------------------
// Attention: one block per (s,b); 4 warps, warp handles query rows t=w,w+4,...
// Packed layout makes the prefix mask implicit.
// ---------------------------------------------------------------------------
__global__ __launch_bounds__(128) void attn_kernel()
{
    __shared__ float qs[SEQT][DH], ks[SEQT][DH], vs[SEQT][DH];
    __shared__ float ps[4][32];

    int q = blockIdx.x;
    int s = q >> 7;
    int b = q & 127;
    int P = s + 1;
    int base = 64 * s * (s + 1) + b * P;
    int tid  = threadIdx.x;
    int w    = tid >> 5;
    int lane = tid & 31;

    for (int h = 0; h < NH; ++h) {
        for (int i = tid; i < P * DH; i += 128) {
            int t = i >> 5, dd = i & 31;
            const float* row = g_qkv + (size_t)(base + t) * (3 * D) + h * DH + dd;
            qs[t][dd] = row[0];
            ks[t][dd] = row[D];
            vs[t][dd] = row[2 * D];
        }
        __syncthreads();

        for (int t = w; t < P; t += 4) {
            float sc = -1e30f;
            if (lane < P) {
                float a = 0.f;
#pragma unroll
                for (int dd = 0; dd < DH; ++dd) a += qs[t][dd] * ks[lane][dd];
                sc = a * 0.17677669529663687f;   // 1/sqrt(32)
            }
            float m = sc;
            for (int o = 16; o; o >>= 1) m = fmaxf(m, __shfl_xor_sync(0xffffffffu, m, o));
            float e = (lane < P) ? expf(sc - m) : 0.f;
            float sum = e;
            for (int o = 16; o; o >>= 1) sum += __shfl_xor_sync(0xffffffffu, sum, o);
            ps[w][lane] = e / sum;
            __syncwarp();
            float c = 0.f;
            for (int j = 0; j < P; ++j) c += ps[w][j] * vs[j][lane];
            g_ctx[(size_t)(base + t) * D + h * DH + lane] = c;
            __syncwarp();
        }
        __syncthreads();
    }
}

// ---------------------------------------------------------------------------
// Residual + LayerNorm (in place): Y = LN(Y + add) * g + b. Warp per token.
// ---------------------------------------------------------------------------
__global__ __launch_bounds__(128) void ln_kernel(
    const float* __restrict__ add, const float* __restrict__ g,
    const float* __restrict__ bb)
{
    int n    = blockIdx.x * 4 + (threadIdx.x >> 5);
    int lane = threadIdx.x & 31;
    float v[4], s = 0.f, s2 = 0.f;
#pragma unroll
    for (int i = 0; i < 4; ++i) {
        int d = lane + 32 * i;
        v[i] = g_Y[(size_t)n * D + d] + add[(size_t)n * D + d];
        s += v[i]; s2 += v[i] * v[i];
    }
    for (int o = 16; o; o >>= 1) {
        s  += __shfl_xor_sync(0xffffffffu, s, o);
        s2 += __shfl_xor_sync(0xffffffffu, s2, o);
    }
    float mean = s * (1.f / 128.f);
    float var  = s2 * (1.f / 128.f) - mean * mean;
    float inv  = rsqrtf(var + 1e-5f);
#pragma unroll
    for (int i = 0; i < 4; ++i) {
        int d = lane + 32 * i;
        g_Y[(size_t)n * D + d] = (v[i] - mean) * inv * g[d] + bb[d];
    }
}

// ---------------------------------------------------------------------------
// Gather the last token of each prefix: g_last[b*T+s] = Y[off(s)+b*(s+1)+s]
// ---------------------------------------------------------------------------
__global__ void gather_kernel()
{
    int n = blockIdx.x;           // b*SEQT + s
    int b = n / SEQT;
    int s = n % SEQT;
    int src = 64 * s * (s + 1) + b * (s + 1) + s;
    g_last[n * D + threadIdx.x] = g_Y[(size_t)src * D + threadIdx.x];
}

// ---------------------------------------------------------------------------
// Classifier + log_softmax: out[n] = log_softmax(relu(last@Wc1^T+bc1)@Wc2^T+bc2)
// ---------------------------------------------------------------------------
__global__ __launch_bounds__(64) void cls_kernel(
    const float* __restrict__ Wc1, const float* __restrict__ bc1,
    const float* __restrict__ Wc2, const float* __restrict__ bc2,
    float* __restrict__ out)
{
    __shared__ float c1[NC];
    __shared__ float lrow[D];
    int n = blockIdx.x;
    int o = threadIdx.x;

    for (int d = o; d < D; d += NC) lrow[d] = g_last[n * D + d];
    __syncthreads();

    float a = bc1[o];
    for (int d = 0; d < D; ++d) a += lrow[d] * Wc1[o * D + d];
    c1[o] = fmaxf(a, 0.f);
    __syncthreads();

    if (o == 0) {
        float l0 = bc2[0], l1 = bc2[1];
        for (int j = 0; j < NC; ++j) {
            l0 += c1[j] * Wc2[j];
            l1 += c1[j] * Wc2[NC + j];
        }
        float m   = fmaxf(l0, l1);
        float lse = m + logf(expf(l0 - m) + expf(l1 - m));
        out[n * 2 + 0] = l0 - lse;
        out[n * 2 + 1] = l1 - lse;
    }
}

// ---------------------------------------------------------------------------
extern "C" void kernel_launch(void* const* d_in, const int* in_sizes, int n_in,
                              void* d_out, int out_size)
{
    const float* x     = (const float*)d_in[0];
    const float* W_fc  = (const float*)d_in[1];
    const float* b_fc  = (const float*)d_in[2];
    const float* qkv_w = (const float*)d_in[3];
    const float* qkv_b = (const float*)d_in[4];
    const float* out_w = (const float*)d_in[5];
    const float* out_b = (const float*)d_in[6];
    const float* ln1_g = (const float*)d_in[7];
    const float* ln1_b = (const float*)d_in[8];
    const float* ln2_g = (const float*)d_in[9];
    const float* ln2_b = (const float*)d_in[10];
    const float* ff1_w = (const float*)d_in[11];
    const float* ff1_b = (const float*)d_in[12];
    const float* ff2_w = (const float*)d_in[13];
    const float* ff2_b = (const float*)d_in[14];
    const float* Wc1   = (const float*)d_in[15];
    const float* bc1   = (const float*)d_in[16];
    const float* Wc2   = (const float*)d_in[17];
    const float* bc2   = (const float*)d_in[18];

    void *p;
    cudaGetSymbolAddress(&p, g_h0);   float* h0   = (float*)p;
    cudaGetSymbolAddress(&p, g_Y);    float* Y    = (float*)p;
    cudaGetSymbolAddress(&p, g_qkv);  float* qkvb = (float*)p;
    cudaGetSymbolAddress(&p, g_ctx);  float* ctx  = (float*)p;
    cudaGetSymbolAddress(&p, g_proj); float* proj = (float*)p;
    cudaGetSymbolAddress(&p, g_H);    float* H    = (float*)p;

    // fc: h0 = relu(x @ W_fc^T + b_fc), then += positional encoding
    sgemm_bias<<<dim3(1, NBT / BM), 256>>>(x, W_fc, b_fc, h0, NBT, D, DIN, 1);
    add_pe_kernel<<<NBT, D>>>();
    scatter_kernel<<<NT, D>>>();

    for (int l = 0; l < 2; ++l) {
        // qkv
        sgemm_bias<<<dim3(3, NT / BM), 256>>>(Y, qkv_w + (size_t)l * 3 * D * D,
                                              qkv_b + l * 3 * D, qkvb, NT, 3 * D, D, 0);
        attn_kernel<<<S_STEPS * BATCH, 128>>>();
        // out projection
        sgemm_bias<<<dim3(1, NT / BM), 256>>>(ctx, out_w + (size_t)l * D * D,
                                              out_b + l * D, proj, NT, D, D, 0);
        ln_kernel<<<NT / 4, 128>>>(proj, ln1_g + l * D, ln1_b + l * D);
        // FFN
        sgemm_bias<<<dim3(DFF / BN, NT / BM), 256>>>(Y, ff1_w + (size_t)l * DFF * D,
                                                     ff1_b + l * DFF, H, NT, DFF, D, 1);
        sgemm_bias<<<dim3(1, NT / BM), 256>>>(H, ff2_w + (size_t)l * D * DFF,
                                              ff2_b + l * D, proj, NT, D, DFF, 0);
        ln_kernel<<<NT / 4, 128>>>(proj, ln2_g + l * D, ln2_b + l * D);
    }

    gather_kernel<<<NBT, D>>>();
    cls_kernel<<<NBT, NC>>>(Wc1, bc1, Wc2, bc2, (float*)d_out);
}

// round 2
// speedup vs baseline: 1.9973x; 1.9973x over previous
#include <cuda_runtime.h>
#include <math.h>
#include <stdint.h>

// Problem constants
#define S_STEPS 24     // number of prefix steps == T
#define BATCH   128
#define SEQT    24
#define DIN     512
#define D       128
#define DFF     2048
#define NH      4
#define DH      32
#define NC      64
#define NT      38400  // BATCH * S*(S+1)/2 = 128*300
#define NBT     3072   // BATCH*SEQT

// Scratch (device globals; allocation-free per harness rules)
__device__ float g_h0[NBT * D];
__device__ float g_Y[NT * D];
__device__ float g_qkv[NT * 3 * D];
__device__ float g_ctx[NT * D];
__device__ float g_proj[NT * D];
__device__ float g_H[(size_t)NT * DFF];
__device__ float g_last[NBT * D];

// ---------------------------------------------------------------------------
// TF32 tensor-core GEMM: C[M,N] = A[M,K] @ W[N,K]^T + bias[N], optional ReLU.
// BM=BN=128, BK=16, 256 threads (8 warps, 4x2), warp tile 32x64,
// mma.sync.m16n8k8 tf32. Requires M%128==0, N%128==0, K%16==0.
// ---------------------------------------------------------------------------
#define BKP 20   // smem row stride (16 + 4 pad) -> conflict-free fragment loads

__device__ __forceinline__ uint32_t f2tf(float f) {
    uint32_t u;
    asm("cvt.rna.tf32.f32 %0, %1;" : "=r"(u) : "f"(f));
    return u;
}

__global__ __launch_bounds__(256) void mma_gemm(
    const float* __restrict__ A, const float* __restrict__ W,
    const float* __restrict__ bias, float* __restrict__ C,
    int M, int N, int K, int relu)
{
    __shared__ uint32_t As[128 * BKP];
    __shared__ uint32_t Bs[128 * BKP];

    const int m0 = blockIdx.y * 128, n0 = blockIdx.x * 128;
    const int t    = threadIdx.x;
    const int warp = t >> 5, lane = t & 31;
    const int g    = lane >> 2, tig = lane & 3;
    const int wm   = (warp >> 1) * 32, wn = (warp & 1) * 64;

    const int r0 = t >> 2;           // 0..63
    const int c4 = (t & 3) * 4;      // 0,4,8,12

    const float* Ap  = A + (size_t)(m0 + r0) * K + c4;
    const float* Ap2 = Ap + (size_t)64 * K;
    const float* Wp  = W + (size_t)(n0 + r0) * K + c4;
    const float* Wp2 = Wp + (size_t)64 * K;

    float4 pa0 = *(const float4*)Ap;
    float4 pa1 = *(const float4*)Ap2;
    float4 pb0 = *(const float4*)Wp;
    float4 pb1 = *(const float4*)Wp2;

    float acc[2][8][4];
#pragma unroll
    for (int i = 0; i < 2; ++i)
#pragma unroll
        for (int j = 0; j < 8; ++j)
#pragma unroll
            for (int k = 0; k < 4; ++k) acc[i][j][k] = 0.f;

    for (int k0 = 0; k0 < K; k0 += 16) {
        uint4 ua0 = make_uint4(f2tf(pa0.x), f2tf(pa0.y), f2tf(pa0.z), f2tf(pa0.w));
        uint4 ua1 = make_uint4(f2tf(pa1.x), f2tf(pa1.y), f2tf(pa1.z), f2tf(pa1.w));
        uint4 ub0 = make_uint4(f2tf(pb0.x), f2tf(pb0.y), f2tf(pb0.z), f2tf(pb0.w));
        uint4 ub1 = make_uint4(f2tf(pb1.x), f2tf(pb1.y), f2tf(pb1.z), f2tf(pb1.w));
        *(uint4*)&As[r0 * BKP + c4]        = ua0;
        *(uint4*)&As[(r0 + 64) * BKP + c4] = ua1;
        *(uint4*)&Bs[r0 * BKP + c4]        = ub0;
        *(uint4*)&Bs[(r0 + 64) * BKP + c4] = ub1;
        __syncthreads();

        if (k0 + 16 < K) {
            pa0 = *(const float4*)(Ap  + k0 + 16);
            pa1 = *(const float4*)(Ap2 + k0 + 16);
            pb0 = *(const float4*)(Wp  + k0 + 16);
            pb1 = *(const float4*)(Wp2 + k0 + 16);
        }

#pragma unroll
        for (int ks = 0; ks < 16; ks += 8) {
            uint32_t af[2][4];
#pragma unroll
            for (int mt = 0; mt < 2; ++mt) {
                int row = wm + mt * 16 + g;
                af[mt][0] = As[row * BKP + ks + tig];
                af[mt][1] = As[(row + 8) * BKP + ks + tig];
                af[mt][2] = As[row * BKP + ks + tig + 4];
                af[mt][3] = As[(row + 8) * BKP + ks + tig + 4];
            }
            uint32_t bf[8][2];
#pragma unroll
            for (int nt = 0; nt < 8; ++nt) {
                int col = wn + nt * 8 + g;
                bf[nt][0] = Bs[col * BKP + ks + tig];
                bf[nt][1] = Bs[col * BKP + ks + tig + 4];
            }
#pragma unroll
            for (int mt = 0; mt < 2; ++mt)
#pragma unroll
                for (int nt = 0; nt < 8; ++nt) {
                    asm volatile(
                        "mma.sync.aligned.m16n8k8.row.col.f32.tf32.tf32.f32 "
                        "{%0,%1,%2,%3}, {%4,%5,%6,%7}, {%8,%9}, {%0,%1,%2,%3};"
                        : "+f"(acc[mt][nt][0]), "+f"(acc[mt][nt][1]),
                          "+f"(acc[mt][nt][2]), "+f"(acc[mt][nt][3])
                        : "r"(af[mt][0]), "r"(af[mt][1]), "r"(af[mt][2]), "r"(af[mt][3]),
                          "r"(bf[nt][0]), "r"(bf[nt][1]));
                }
        }
        __syncthreads();
    }

#pragma unroll
    for (int mt = 0; mt < 2; ++mt) {
#pragma unroll
        for (int nt = 0; nt < 8; ++nt) {
            int col = n0 + wn + nt * 8 + 2 * tig;
            float b0v = bias[col], b1v = bias[col + 1];
            int row = m0 + wm + mt * 16 + g;
            float2 v0 = make_float2(acc[mt][nt][0] + b0v, acc[mt][nt][1] + b1v);
            float2 v1 = make_float2(acc[mt][nt][2] + b0v, acc[mt][nt][3] + b1v);
            if (relu) {
                v0.x = fmaxf(v0.x, 0.f); v0.y = fmaxf(v0.y, 0.f);
                v1.x = fmaxf(v1.x, 0.f); v1.y = fmaxf(v1.y, 0.f);
            }
            *(float2*)(C + (size_t)row * N + col)       = v0;
            *(float2*)(C + (size_t)(row + 8) * N + col) = v1;
        }
    }
}

// ---------------------------------------------------------------------------
// Positional encoding add: g_h0[b*T+t][d] += pe(t,d)
// ---------------------------------------------------------------------------
__global__ void add_pe_kernel()
{
    int n = blockIdx.x;           // b*SEQT + t
    int t = n % SEQT;
    int d = threadIdx.x;          // 0..127
    float freq = expf((float)(d & ~1) * (-9.210340371976184f / 128.f));
    float arg  = (float)t * freq;
    float pe   = (d & 1) ? cosf(arg) : sinf(arg);
    g_h0[n * D + d] += pe;
}

// ---------------------------------------------------------------------------
// Scatter h0 to packed token layout: token n -> (s, b, t)
// off(s) = 64*s*(s+1); within step: b*(s+1)+t
// ---------------------------------------------------------------------------
__global__ void scatter_kernel()
{
    int n = blockIdx.x;
    int s = 0;
    while (n >= 64 * (s + 1) * (s + 2)) s++;
    int r = n - 64 * s * (s + 1);
    int P = s + 1;
    int b = r / P;
    int t = r - b * P;
    g_Y[n * D + threadIdx.x] = g_h0[(b * SEQT + t) * D + threadIdx.x];
}

// ---------------------------------------------------------------------------
// Attention: one block per (s,b); 4 warps, warp handles query rows t=w,w+4,...
// Packed layout makes the prefix mask implicit.
// ---------------------------------------------------------------------------
__global__ __launch_bounds__(128) void attn_kernel()
{
    __shared__ float qs[SEQT][DH], ks[SEQT][DH], vs[SEQT][DH];
    __shared__ float ps[4][32];

    int q = blockIdx.x;
    int s = q >> 7;
    int b = q & 127;
    int P = s + 1;
    int base = 64 * s * (s + 1) + b * P;
    int tid  = threadIdx.x;
    int w    = tid >> 5;
    int lane = tid & 31;

    for (int h = 0; h < NH; ++h) {
        for (int i = tid; i < P * DH; i += 128) {
            int t = i >> 5, dd = i & 31;
            const float* row = g_qkv + (size_t)(base + t) * (3 * D) + h * DH + dd;
            qs[t][dd] = row[0];
            ks[t][dd] = row[D];
            vs[t][dd] = row[2 * D];
        }
        __syncthreads();

        for (int t = w; t < P; t += 4) {
            float sc = -1e30f;
            if (lane < P) {
                float a = 0.f;
#pragma unroll
                for (int dd = 0; dd < DH; ++dd) a += qs[t][dd] * ks[lane][dd];
                sc = a * 0.17677669529663687f;   // 1/sqrt(32)
            }
            float m = sc;
            for (int o = 16; o; o >>= 1) m = fmaxf(m, __shfl_xor_sync(0xffffffffu, m, o));
            float e = (lane < P) ? expf(sc - m) : 0.f;
            float sum = e;
            for (int o = 16; o; o >>= 1) sum += __shfl_xor_sync(0xffffffffu, sum, o);
            ps[w][lane] = e / sum;
            __syncwarp();
            float c = 0.f;
            for (int j = 0; j < P; ++j) c += ps[w][j] * vs[j][lane];
            g_ctx[(size_t)(base + t) * D + h * DH + lane] = c;
            __syncwarp();
        }
        __syncthreads();
    }
}

// ---------------------------------------------------------------------------
// Residual + LayerNorm (in place): Y = LN(Y + add) * g + b. Warp per token.
// ---------------------------------------------------------------------------
__global__ __launch_bounds__(128) void ln_kernel(
    const float* __restrict__ add, const float* __restrict__ g,
    const float* __restrict__ bb)
{
    int n    = blockIdx.x * 4 + (threadIdx.x >> 5);
    int lane = threadIdx.x & 31;
    float v[4], s = 0.f, s2 = 0.f;
#pragma unroll
    for (int i = 0; i < 4; ++i) {
        int d = lane + 32 * i;
        v[i] = g_Y[(size_t)n * D + d] + add[(size_t)n * D + d];
        s += v[i]; s2 += v[i] * v[i];
    }
    for (int o = 16; o; o >>= 1) {
        s  += __shfl_xor_sync(0xffffffffu, s, o);
        s2 += __shfl_xor_sync(0xffffffffu, s2, o);
    }
    float mean = s * (1.f / 128.f);
    float var  = s2 * (1.f / 128.f) - mean * mean;
    float inv  = rsqrtf(var + 1e-5f);
#pragma unroll
    for (int i = 0; i < 4; ++i) {
        int d = lane + 32 * i;
        g_Y[(size_t)n * D + d] = (v[i] - mean) * inv * g[d] + bb[d];
    }
}

// ---------------------------------------------------------------------------
// Gather the last token of each prefix: g_last[b*T+s] = Y[off(s)+b*(s+1)+s]
// ---------------------------------------------------------------------------
__global__ void gather_kernel()
{
    int n = blockIdx.x;           // b*SEQT + s
    int b = n / SEQT;
    int s = n % SEQT;
    int src = 64 * s * (s + 1) + b * (s + 1) + s;
    g_last[n * D + threadIdx.x] = g_Y[(size_t)src * D + threadIdx.x];
}

// ---------------------------------------------------------------------------
// Classifier + log_softmax (fp32): out[n] = log_softmax(relu(last@Wc1^T+bc1)@Wc2^T+bc2)
// ---------------------------------------------------------------------------
__global__ __launch_bounds__(64) void cls_kernel(
    const float* __restrict__ Wc1, const float* __restrict__ bc1,
    const float* __restrict__ Wc2, const float* __restrict__ bc2,
    float* __restrict__ out)
{
    __shared__ float c1[NC];
    __shared__ float lrow[D];
    int n = blockIdx.x;
    int o = threadIdx.x;

    for (int d = o; d < D; d += NC) lrow[d] = g_last[n * D + d];
    __syncthreads();

    float a = bc1[o];
    for (int d = 0; d < D; ++d) a += lrow[d] * Wc1[o * D + d];
    c1[o] = fmaxf(a, 0.f);
    __syncthreads();

    if (o == 0) {
        float l0 = bc2[0], l1 = bc2[1];
        for (int j = 0; j < NC; ++j) {
            l0 += c1[j] * Wc2[j];
            l1 += c1[j] * Wc2[NC + j];
        }
        float m   = fmaxf(l0, l1);
        float lse = m + logf(expf(l0 - m) + expf(l1 - m));
        out[n * 2 + 0] = l0 - lse;
        out[n * 2 + 1] = l1 - lse;
    }
}

// ---------------------------------------------------------------------------
extern "C" void kernel_launch(void* const* d_in, const int* in_sizes, int n_in,
                              void* d_out, int out_size)
{
    const float* x     = (const float*)d_in[0];
    const float* W_fc  = (const float*)d_in[1];
    const float* b_fc  = (const float*)d_in[2];
    const float* qkv_w = (const float*)d_in[3];
    const float* qkv_b = (const float*)d_in[4];
    const float* out_w = (const float*)d_in[5];
    const float* out_b = (const float*)d_in[6];
    const float* ln1_g = (const float*)d_in[7];
    const float* ln1_b = (const float*)d_in[8];
    const float* ln2_g = (const float*)d_in[9];
    const float* ln2_b = (const float*)d_in[10];
    const float* ff1_w = (const float*)d_in[11];
    const float* ff1_b = (const float*)d_in[12];
    const float* ff2_w = (const float*)d_in[13];
    const float* ff2_b = (const float*)d_in[14];
    const float* Wc1   = (const float*)d_in[15];
    const float* bc1   = (const float*)d_in[16];
    const float* Wc2   = (const float*)d_in[17];
    const float* bc2   = (const float*)d_in[18];

    void *p;
    cudaGetSymbolAddress(&p, g_h0);   float* h0   = (float*)p;
    cudaGetSymbolAddress(&p, g_Y);    float* Y    = (float*)p;
    cudaGetSymbolAddress(&p, g_qkv);  float* qkvb = (float*)p;
    cudaGetSymbolAddress(&p, g_ctx);  float* ctx  = (float*)p;
    cudaGetSymbolAddress(&p, g_proj); float* proj = (float*)p;
    cudaGetSymbolAddress(&p, g_H);    float* H    = (float*)p;

    // fc: h0 = relu(x @ W_fc^T + b_fc), then += positional encoding
    mma_gemm<<<dim3(1, NBT / 128), 256>>>(x, W_fc, b_fc, h0, NBT, D, DIN, 1);
    add_pe_kernel<<<NBT, D>>>();
    scatter_kernel<<<NT, D>>>();

    for (int l = 0; l < 2; ++l) {
        // qkv
        mma_gemm<<<dim3(3, NT / 128), 256>>>(Y, qkv_w + (size_t)l * 3 * D * D,
                                             qkv_b + l * 3 * D, qkvb, NT, 3 * D, D, 0);
        attn_kernel<<<S_STEPS * BATCH, 128>>>();
        // out projection
        mma_gemm<<<dim3(1, NT / 128), 256>>>(ctx, out_w + (size_t)l * D * D,
                                             out_b + l * D, proj, NT, D, D, 0);
        ln_kernel<<<NT / 4, 128>>>(proj, ln1_g + l * D, ln1_b + l * D);
        // FFN
        mma_gemm<<<dim3(DFF / 128, NT / 128), 256>>>(Y, ff1_w + (size_t)l * DFF * D,
                                                     ff1_b + l * DFF, H, NT, DFF, D, 1);
        mma_gemm<<<dim3(1, NT / 128), 256>>>(H, ff2_w + (size_t)l * D * DFF,
                                             ff2_b + l * D, proj, NT, D, DFF, 0);
        ln_kernel<<<NT / 4, 128>>>(proj, ln2_g + l * D, ln2_b + l * D);
    }

    gather_kernel<<<NBT, D>>>();
    cls_kernel<<<NBT, NC>>>(Wc1, bc1, Wc2, bc2, (float*)d_out);
}

// round 3
// speedup vs baseline: 2.9881x; 1.4960x over previous
#include <cuda_runtime.h>
#include <cuda_bf16.h>
#include <math.h>
#include <stdint.h>

// Problem constants
#define S_STEPS 24
#define BATCH   128
#define SEQT    24
#define DIN     512
#define D       128
#define DFF     2048
#define NH      4
#define DH      32
#define NC      64
#define NT      38400  // BATCH * S*(S+1)/2
#define NBT     3072   // BATCH*SEQT

// fp32 scratch
__device__ float g_h0[NBT * D];
__device__ float g_Y[NT * D];
__device__ float g_qkv[NT * 3 * D];
__device__ float g_proj[NT * D];
__device__ float g_last[NBT * D];

// bf16 shadow buffers
__device__ __nv_bfloat16 g_xbf[NBT * DIN];
__device__ __nv_bfloat16 g_wfc_bf[D * DIN];
__device__ __nv_bfloat16 g_qkvw_bf[2 * 3 * D * D];
__device__ __nv_bfloat16 g_outw_bf[2 * D * D];
__device__ __nv_bfloat16 g_ff1w_bf[2 * DFF * D];
__device__ __nv_bfloat16 g_ff2w_bf[2 * D * DFF];
__device__ __nv_bfloat16 g_Ybf[NT * D];
__device__ __nv_bfloat16 g_ctxbf[NT * D];
__device__ __nv_bfloat16 g_Hbf[(size_t)NT * DFF];

__device__ __forceinline__ uint32_t smem_u32(const void* p) {
    return (uint32_t)__cvta_generic_to_shared(p);
}

// ---------------------------------------------------------------------------
// bf16 tensor-core GEMM: C[M,N] = A[M,K] @ W[N,K]^T + bias, optional ReLU.
// BM=BN=128, BK=32, 256 threads (8 warps, 4x2), warp tile 32x64.
// cp.async double buffering + ldmatrix fragment loads. M%128, N%128, K%32 == 0.
// Writes fp32 Cf and/or bf16 Cb (either may be null).
// ---------------------------------------------------------------------------
#define SSTR 40   // smem row stride in bf16 elems (32 + 8 pad) -> LDSM conflict-free

__global__ __launch_bounds__(256) void mma_gemm_bf16(
    const __nv_bfloat16* __restrict__ A, const __nv_bfloat16* __restrict__ W,
    const float* __restrict__ bias, float* __restrict__ Cf,
    __nv_bfloat16* __restrict__ Cb, int M, int N, int K, int relu)
{
    __shared__ __align__(16) __nv_bfloat16 As[2][128 * SSTR];
    __shared__ __align__(16) __nv_bfloat16 Bs[2][128 * SSTR];

    const int m0 = blockIdx.y * 128, n0 = blockIdx.x * 128;
    const int t = threadIdx.x, warp = t >> 5, lane = t & 31;
    const int g = lane >> 2, tig = lane & 3;
    const int wm = (warp >> 1) * 32, wn = (warp & 1) * 64;

    const int ldrow = t >> 2;        // 0..63 (r adds 64)
    const int ldch  = (t & 3) * 8;   // element offset within row (8 bf16 = 16B)

    // ldmatrix lane->address mapping (x4 over a 16x16 bf16 tile)
    const int xr = (lane < 16) ? lane : (lane - 16);
    const int xc = (lane < 16) ? 0 : 8;

    float acc[2][8][4];
#pragma unroll
    for (int i = 0; i < 2; ++i)
#pragma unroll
        for (int j = 0; j < 8; ++j)
#pragma unroll
            for (int k = 0; k < 4; ++k) acc[i][j][k] = 0.f;

    auto issue = [&](int k0, int buf) {
#pragma unroll
        for (int r = 0; r < 2; ++r) {
            int row = ldrow + 64 * r;
            const __nv_bfloat16* ga = A + (size_t)(m0 + row) * K + k0 + ldch;
            uint32_t sa = smem_u32(&As[buf][row * SSTR + ldch]);
            asm volatile("cp.async.cg.shared.global [%0], [%1], 16;" :: "r"(sa), "l"(ga));
            const __nv_bfloat16* gb = W + (size_t)(n0 + row) * K + k0 + ldch;
            uint32_t sb = smem_u32(&Bs[buf][row * SSTR + ldch]);
            asm volatile("cp.async.cg.shared.global [%0], [%1], 16;" :: "r"(sb), "l"(gb));
        }
        asm volatile("cp.async.commit_group;");
    };

    issue(0, 0);
    const int KT = K >> 5;
    int buf = 0;
    for (int kt = 0; kt < KT; ++kt) {
        asm volatile("cp.async.wait_group 0;");
        __syncthreads();
        if (kt + 1 < KT) issue((kt + 1) << 5, buf ^ 1);

#pragma unroll
        for (int ks = 0; ks < 32; ks += 16) {
            uint32_t af[2][4];
#pragma unroll
            for (int mt = 0; mt < 2; ++mt) {
                uint32_t ad = smem_u32(&As[buf][(wm + mt * 16 + xr) * SSTR + ks + xc]);
                asm volatile("ldmatrix.sync.aligned.m8n8.x4.shared.b16 {%0,%1,%2,%3},[%4];"
                    : "=r"(af[mt][0]), "=r"(af[mt][1]), "=r"(af[mt][2]), "=r"(af[mt][3])
                    : "r"(ad));
            }
            uint32_t bfr[8][2];
#pragma unroll
            for (int np = 0; np < 4; ++np) {
                uint32_t bd = smem_u32(&Bs[buf][(wn + np * 16 + xr) * SSTR + ks + xc]);
                uint32_t r0, r1, r2, r3;
                asm volatile("ldmatrix.sync.aligned.m8n8.x4.shared.b16 {%0,%1,%2,%3},[%4];"
                    : "=r"(r0), "=r"(r1), "=r"(r2), "=r"(r3) : "r"(bd));
                bfr[2 * np][0] = r0; bfr[2 * np + 1][0] = r1;
                bfr[2 * np][1] = r2; bfr[2 * np + 1][1] = r3;
            }
#pragma unroll
            for (int mt = 0; mt < 2; ++mt)
#pragma unroll
                for (int nt = 0; nt < 8; ++nt) {
                    asm volatile(
                        "mma.sync.aligned.m16n8k16.row.col.f32.bf16.bf16.f32 "
                        "{%0,%1,%2,%3},{%4,%5,%6,%7},{%8,%9},{%0,%1,%2,%3};"
                        : "+f"(acc[mt][nt][0]), "+f"(acc[mt][nt][1]),
                          "+f"(acc[mt][nt][2]), "+f"(acc[mt][nt][3])
                        : "r"(af[mt][0]), "r"(af[mt][1]), "r"(af[mt][2]), "r"(af[mt][3]),
                          "r"(bfr[nt][0]), "r"(bfr[nt][1]));
                }
        }
        __syncthreads();
        buf ^= 1;
    }

#pragma unroll
    for (int mt = 0; mt < 2; ++mt) {
#pragma unroll
        for (int nt = 0; nt < 8; ++nt) {
            int col = n0 + wn + nt * 8 + 2 * tig;
            float b0v = bias[col], b1v = bias[col + 1];
            int row = m0 + wm + mt * 16 + g;
            float2 v0 = make_float2(acc[mt][nt][0] + b0v, acc[mt][nt][1] + b1v);
            float2 v1 = make_float2(acc[mt][nt][2] + b0v, acc[mt][nt][3] + b1v);
            if (relu) {
                v0.x = fmaxf(v0.x, 0.f); v0.y = fmaxf(v0.y, 0.f);
                v1.x = fmaxf(v1.x, 0.f); v1.y = fmaxf(v1.y, 0.f);
            }
            if (Cf) {
                *(float2*)(Cf + (size_t)row * N + col)       = v0;
                *(float2*)(Cf + (size_t)(row + 8) * N + col) = v1;
            }
            if (Cb) {
                *(__nv_bfloat162*)(Cb + (size_t)row * N + col) =
                    __floats2bfloat162_rn(v0.x, v0.y);
                *(__nv_bfloat162*)(Cb + (size_t)(row + 8) * N + col) =
                    __floats2bfloat162_rn(v1.x, v1.y);
            }
        }
    }
}

// ---------------------------------------------------------------------------
// fp32 -> bf16 conversion (n % 4 == 0)
// ---------------------------------------------------------------------------
__global__ void f2bf(const float* __restrict__ s, __nv_bfloat16* __restrict__ d, int n)
{
    int i = (blockIdx.x * 256 + threadIdx.x) * 4;
    if (i < n) {
        float4 v = *(const float4*)(s + i);
        *(__nv_bfloat162*)(d + i)     = __floats2bfloat162_rn(v.x, v.y);
        *(__nv_bfloat162*)(d + i + 2) = __floats2bfloat162_rn(v.z, v.w);
    }
}

// ---------------------------------------------------------------------------
// Positional encoding add (fp32 h0)
// ---------------------------------------------------------------------------
__global__ void add_pe_kernel()
{
    int n = blockIdx.x;
    int t = n % SEQT;
    int d = threadIdx.x;
    float freq = expf((float)(d & ~1) * (-9.210340371976184f / 128.f));
    float arg  = (float)t * freq;
    float pe   = (d & 1) ? cosf(arg) : sinf(arg);
    g_h0[n * D + d] += pe;
}

// ---------------------------------------------------------------------------
// Scatter h0 -> packed tokens; writes fp32 Y and bf16 shadow
// ---------------------------------------------------------------------------
__global__ void scatter_kernel()
{
    int n = blockIdx.x;
    int s = 0;
    while (n >= 64 * (s + 1) * (s + 2)) s++;
    int r = n - 64 * s * (s + 1);
    int P = s + 1;
    int b = r / P;
    int t = r - b * P;
    float v = g_h0[(b * SEQT + t) * D + threadIdx.x];
    g_Y[n * D + threadIdx.x]   = v;
    g_Ybf[n * D + threadIdx.x] = __float2bfloat16(v);
}

// ---------------------------------------------------------------------------
// Attention (fp32 math), writes ctx as bf16
// ---------------------------------------------------------------------------
__global__ __launch_bounds__(128) void attn_kernel()
{
    __shared__ float qs[SEQT][DH], ks[SEQT][DH], vs[SEQT][DH];
    __shared__ float ps[4][32];

    int q = blockIdx.x;
    int s = q >> 7;
    int b = q & 127;
    int P = s + 1;
    int base = 64 * s * (s + 1) + b * P;
    int tid  = threadIdx.x;
    int w    = tid >> 5;
    int lane = tid & 31;

    for (int h = 0; h < NH; ++h) {
        for (int i = tid; i < P * DH; i += 128) {
            int t = i >> 5, dd = i & 31;
            const float* row = g_qkv + (size_t)(base + t) * (3 * D) + h * DH + dd;
            qs[t][dd] = row[0];
            ks[t][dd] = row[D];
            vs[t][dd] = row[2 * D];
        }
        __syncthreads();

        for (int t = w; t < P; t += 4) {
            float sc = -1e30f;
            if (lane < P) {
                float a = 0.f;
#pragma unroll
                for (int dd = 0; dd < DH; ++dd) a += qs[t][dd] * ks[lane][dd];
                sc = a * 0.17677669529663687f;
            }
            float m = sc;
            for (int o = 16; o; o >>= 1) m = fmaxf(m, __shfl_xor_sync(0xffffffffu, m, o));
            float e = (lane < P) ? expf(sc - m) : 0.f;
            float sum = e;
            for (int o = 16; o; o >>= 1) sum += __shfl_xor_sync(0xffffffffu, sum, o);
            ps[w][lane] = e / sum;
            __syncwarp();
            float c = 0.f;
            for (int j = 0; j < P; ++j) c += ps[w][j] * vs[j][lane];
            g_ctxbf[(size_t)(base + t) * D + h * DH + lane] = __float2bfloat16(c);
            __syncwarp();
        }
        __syncthreads();
    }
}

// ---------------------------------------------------------------------------
// Residual + LayerNorm (in place on fp32 Y), also writes bf16 shadow
// ---------------------------------------------------------------------------
__global__ __launch_bounds__(128) void ln_kernel(
    const float* __restrict__ add, const float* __restrict__ g,
    const float* __restrict__ bb)
{
    int n    = blockIdx.x * 4 + (threadIdx.x >> 5);
    int lane = threadIdx.x & 31;
    float v[4], s = 0.f, s2 = 0.f;
#pragma unroll
    for (int i = 0; i < 4; ++i) {
        int d = lane + 32 * i;
        v[i] = g_Y[(size_t)n * D + d] + add[(size_t)n * D + d];
        s += v[i]; s2 += v[i] * v[i];
    }
    for (int o = 16; o; o >>= 1) {
        s  += __shfl_xor_sync(0xffffffffu, s, o);
        s2 += __shfl_xor_sync(0xffffffffu, s2, o);
    }
    float mean = s * (1.f / 128.f);
    float var  = s2 * (1.f / 128.f) - mean * mean;
    float inv  = rsqrtf(var + 1e-5f);
#pragma unroll
    for (int i = 0; i < 4; ++i) {
        int d = lane + 32 * i;
        float o = (v[i] - mean) * inv * g[d] + bb[d];
        g_Y[(size_t)n * D + d]   = o;
        g_Ybf[(size_t)n * D + d] = __float2bfloat16(o);
    }
}

// ---------------------------------------------------------------------------
__global__ void gather_kernel()
{
    int n = blockIdx.x;
    int b = n / SEQT;
    int s = n % SEQT;
    int src = 64 * s * (s + 1) + b * (s + 1) + s;
    g_last[n * D + threadIdx.x] = g_Y[(size_t)src * D + threadIdx.x];
}

// ---------------------------------------------------------------------------
// Classifier + log_softmax (fp32)
// ---------------------------------------------------------------------------
__global__ __launch_bounds__(64) void cls_kernel(
    const float* __restrict__ Wc1, const float* __restrict__ bc1,
    const float* __restrict__ Wc2, const float* __restrict__ bc2,
    float* __restrict__ out)
{
    __shared__ float c1[NC];
    __shared__ float lrow[D];
    int n = blockIdx.x;
    int o = threadIdx.x;

    for (int d = o; d < D; d += NC) lrow[d] = g_last[n * D + d];
    __syncthreads();

    float a = bc1[o];
    for (int d = 0; d < D; ++d) a += lrow[d] * Wc1[o * D + d];
    c1[o] = fmaxf(a, 0.f);
    __syncthreads();

    if (o == 0) {
        float l0 = bc2[0], l1 = bc2[1];
        for (int j = 0; j < NC; ++j) {
            l0 += c1[j] * Wc2[j];
            l1 += c1[j] * Wc2[NC + j];
        }
        float m   = fmaxf(l0, l1);
        float lse = m + logf(expf(l0 - m) + expf(l1 - m));
        out[n * 2 + 0] = l0 - lse;
        out[n * 2 + 1] = l1 - lse;
    }
}

// ---------------------------------------------------------------------------
extern "C" void kernel_launch(void* const* d_in, const int* in_sizes, int n_in,
                              void* d_out, int out_size)
{
    const float* x     = (const float*)d_in[0];
    const float* W_fc  = (const float*)d_in[1];
    const float* b_fc  = (const float*)d_in[2];
    const float* qkv_w = (const float*)d_in[3];
    const float* qkv_b = (const float*)d_in[4];
    const float* out_w = (const float*)d_in[5];
    const float* out_b = (const float*)d_in[6];
    const float* ln1_g = (const float*)d_in[7];
    const float* ln1_b = (const float*)d_in[8];
    const float* ln2_g = (const float*)d_in[9];
    const float* ln2_b = (const float*)d_in[10];
    const float* ff1_w = (const float*)d_in[11];
    const float* ff1_b = (const float*)d_in[12];
    const float* ff2_w = (const float*)d_in[13];
    const float* ff2_b = (const float*)d_in[14];
    const float* Wc1   = (const float*)d_in[15];
    const float* bc1   = (const float*)d_in[16];
    const float* Wc2   = (const float*)d_in[17];
    const float* bc2   = (const float*)d_in[18];

    void* p;
    cudaGetSymbolAddress(&p, g_h0);      float* h0    = (float*)p;
    cudaGetSymbolAddress(&p, g_qkv);     float* qkvb  = (float*)p;
    cudaGetSymbolAddress(&p, g_proj);    float* proj  = (float*)p;
    cudaGetSymbolAddress(&p, g_xbf);     __nv_bfloat16* xbf   = (__nv_bfloat16*)p;
    cudaGetSymbolAddress(&p, g_wfc_bf);  __nv_bfloat16* wfcb  = (__nv_bfloat16*)p;
    cudaGetSymbolAddress(&p, g_qkvw_bf); __nv_bfloat16* qkvwb = (__nv_bfloat16*)p;
    cudaGetSymbolAddress(&p, g_outw_bf); __nv_bfloat16* outwb = (__nv_bfloat16*)p;
    cudaGetSymbolAddress(&p, g_ff1w_bf); __nv_bfloat16* ff1wb = (__nv_bfloat16*)p;
    cudaGetSymbolAddress(&p, g_ff2w_bf); __nv_bfloat16* ff2wb = (__nv_bfloat16*)p;
    cudaGetSymbolAddress(&p, g_Ybf);     __nv_bfloat16* ybf   = (__nv_bfloat16*)p;
    cudaGetSymbolAddress(&p, g_ctxbf);   __nv_bfloat16* ctxb  = (__nv_bfloat16*)p;
    cudaGetSymbolAddress(&p, g_Hbf);     __nv_bfloat16* hbf   = (__nv_bfloat16*)p;

    auto cvt = [&](const float* s, __nv_bfloat16* d, int n) {
        f2bf<<<(n / 4 + 255) / 256, 256>>>(s, d, n);
    };
    cvt(x,     xbf,   NBT * DIN);
    cvt(W_fc,  wfcb,  D * DIN);
    cvt(qkv_w, qkvwb, 2 * 3 * D * D);
    cvt(out_w, outwb, 2 * D * D);
    cvt(ff1_w, ff1wb, 2 * DFF * D);
    cvt(ff2_w, ff2wb, 2 * D * DFF);

    // fc: h0 = relu(x @ W_fc^T + b_fc) (fp32 out), then += PE, scatter
    mma_gemm_bf16<<<dim3(1, NBT / 128), 256>>>(xbf, wfcb, b_fc, h0, nullptr,
                                               NBT, D, DIN, 1);
    add_pe_kernel<<<NBT, D>>>();
    scatter_kernel<<<NT, D>>>();

    for (int l = 0; l < 2; ++l) {
        mma_gemm_bf16<<<dim3(3, NT / 128), 256>>>(ybf, qkvwb + (size_t)l * 3 * D * D,
                                                  qkv_b + l * 3 * D, qkvb, nullptr,
                                                  NT, 3 * D, D, 0);
        attn_kernel<<<S_STEPS * BATCH, 128>>>();
        mma_gemm_bf16<<<dim3(1, NT / 128), 256>>>(ctxb, outwb + (size_t)l * D * D,
                                                  out_b + l * D, proj, nullptr,
                                                  NT, D, D, 0);
        ln_kernel<<<NT / 4, 128>>>(proj, ln1_g + l * D, ln1_b + l * D);
        mma_gemm_bf16<<<dim3(DFF / 128, NT / 128), 256>>>(ybf, ff1wb + (size_t)l * DFF * D,
                                                          ff1_b + l * DFF, nullptr, hbf,
                                                          NT, DFF, D, 1);
        mma_gemm_bf16<<<dim3(1, NT / 128), 256>>>(hbf, ff2wb + (size_t)l * D * DFF,
                                                  ff2_b + l * D, proj, nullptr,
                                                  NT, D, DFF, 0);
        ln_kernel<<<NT / 4, 128>>>(proj, ln2_g + l * D, ln2_b + l * D);
    }

    gather_kernel<<<NBT, D>>>();
    cls_kernel<<<NBT, NC>>>(Wc1, bc1, Wc2, bc2, (float*)d_out);
}